// round 11
// baseline (speedup 1.0000x reference)
#include <cuda_runtime.h>
#include <cuda_bf16.h>
#include <cuda_fp16.h>
#include <cstdint>
#include <math_constants.h>

#define NN 100000
#define EE 1600000
#define NBLK 98

// ---------------- scratch ---------------------------------------------------
__device__ float  g_h[(size_t)NN * 128];
__device__ float  g_q[(size_t)NN * 128];   // head-major: [n][h][d]
__device__ __half g_k[(size_t)NN * 128];   // head-major
__device__ __half g_v[(size_t)NN * 128];   // head-major
__device__ int    g_csrcol[EE];
__device__ int    g_rowptr[NN + 1];
__device__ int    g_cnt[NN];
__device__ int    g_bsum[NBLK];
__device__ int    g_boff[NBLK];
__device__ __nv_bfloat16 g_wt_hi[4 * 128 * 128];  // W^T, [w][n][k]
__device__ __nv_bfloat16 g_wt_lo[4 * 128 * 128];

// ---------------- helpers ---------------------------------------------------
__device__ __forceinline__ uint32_t smem_u32(const void* p) {
    uint32_t a;
    asm("{ .reg .u64 t; cvta.to.shared.u64 t, %1; cvt.u32.u64 %0, t; }"
        : "=r"(a) : "l"(p));
    return a;
}
__device__ __forceinline__ void ldm_x4(uint32_t& r0, uint32_t& r1,
                                       uint32_t& r2, uint32_t& r3, uint32_t addr) {
    asm volatile("ldmatrix.sync.aligned.m8n8.x4.shared.b16 {%0,%1,%2,%3}, [%4];"
                 : "=r"(r0), "=r"(r1), "=r"(r2), "=r"(r3) : "r"(addr));
}
__device__ __forceinline__ void mma_bf16(float* c, const uint32_t* a,
                                         uint32_t b0, uint32_t b1) {
    asm volatile(
        "mma.sync.aligned.m16n8k16.row.col.f32.bf16.bf16.f32 "
        "{%0,%1,%2,%3}, {%4,%5,%6,%7}, {%8,%9}, {%0,%1,%2,%3};"
        : "+f"(c[0]), "+f"(c[1]), "+f"(c[2]), "+f"(c[3])
        : "r"(a[0]), "r"(a[1]), "r"(a[2]), "r"(a[3]), "r"(b0), "r"(b1));
}
__device__ __forceinline__ unsigned pack_bf2(float x, float y) {
    __nv_bfloat162 t = __floats2bfloat162_rn(x, y);
    return *reinterpret_cast<unsigned*>(&t);
}
__device__ __forceinline__ void cp16(uint32_t dst, const void* src) {
    asm volatile("cp.async.cg.shared.global [%0], [%1], 16;"
                 :: "r"(dst), "l"(src) : "memory");
}
#define CP_COMMIT() asm volatile("cp.async.commit_group;" ::: "memory")
#define CP_WAIT0()  asm volatile("cp.async.wait_group 0;" ::: "memory")

// 16-dim fp32 dot of q (fp32 regs) with 16 halves packed in two uint4
__device__ __forceinline__ float dot16(const float* qd, uint4 lo, uint4 hi) {
    uint32_t wbuf[8] = {lo.x, lo.y, lo.z, lo.w, hi.x, hi.y, hi.z, hi.w};
    float d = 0.f;
#pragma unroll
    for (int j = 0; j < 8; j++) {
        float2 f = __half22float2(*reinterpret_cast<const __half2*>(&wbuf[j]));
        d = fmaf(qd[2 * j], f.x, d);
        d = fmaf(qd[2 * j + 1], f.y, d);
    }
    return d;
}
__device__ __forceinline__ void acc16(float* acc, float p, uint4 lo, uint4 hi) {
    uint32_t wbuf[8] = {lo.x, lo.y, lo.z, lo.w, hi.x, hi.y, hi.z, hi.w};
#pragma unroll
    for (int j = 0; j < 8; j++) {
        float2 f = __half22float2(*reinterpret_cast<const __half2*>(&wbuf[j]));
        acc[2 * j]     = fmaf(p, f.x, acc[2 * j]);
        acc[2 * j + 1] = fmaf(p, f.y, acc[2 * j + 1]);
    }
}

// ================= prep: zero cnt + transpose/convert weights ===============
__global__ void k_prep(const float* __restrict__ W0, const float* __restrict__ W1,
                       const float* __restrict__ W2, const float* __restrict__ W3) {
    if (blockIdx.x < 391) {
        int i = blockIdx.x * 256 + threadIdx.x;
        if (i < NN) g_cnt[i] = 0;
    } else {
        int j = (blockIdx.x - 391) * 256 + threadIdx.x;  // [0, 65536)
        int w = j >> 14, rem = j & 16383;
        int n = rem >> 7, kk = rem & 127;
        const float* Wp = (w == 0) ? W0 : (w == 1) ? W1 : (w == 2) ? W2 : W3;
        float val = Wp[kk * 128 + n];
        float hi = __bfloat162float(__float2bfloat16_rn(val));
        g_wt_hi[j] = __float2bfloat16_rn(val);
        g_wt_lo[j] = __float2bfloat16_rn(val - hi);
    }
}

// ================= CSR build ===============================================
__global__ void k_hist(const int* __restrict__ rows) {
    int e = blockIdx.x * blockDim.x + threadIdx.x;
    if (e < EE) atomicAdd(&g_cnt[rows[e]], 1);
}

__global__ void __launch_bounds__(256) k_scan_block() {
    __shared__ int ws[8];
    int b = blockIdx.x, t = threadIdx.x;
    int i0 = b * 1024 + t * 4;
    int v0 = 0, v1 = 0, v2 = 0, v3 = 0;
    if (i0 < NN) {
        if (i0 + 3 < NN) {
            int4 vv = *reinterpret_cast<const int4*>(&g_cnt[i0]);
            v0 = vv.x; v1 = vv.y; v2 = vv.z; v3 = vv.w;
            *reinterpret_cast<int4*>(&g_cnt[i0]) = make_int4(0, 0, 0, 0);
        } else {
            v0 = g_cnt[i0]; g_cnt[i0] = 0;
            if (i0 + 1 < NN) { v1 = g_cnt[i0 + 1]; g_cnt[i0 + 1] = 0; }
            if (i0 + 2 < NN) { v2 = g_cnt[i0 + 2]; g_cnt[i0 + 2] = 0; }
        }
    }
    int tsum = v0 + v1 + v2 + v3;
    int lane = t & 31, wid = t >> 5;
    int x = tsum;
#pragma unroll
    for (int m = 1; m < 32; m <<= 1) {
        int y = __shfl_up_sync(0xffffffffu, x, m);
        if (lane >= m) x += y;
    }
    if (lane == 31) ws[wid] = x;
    __syncthreads();
    if (t == 0) {
        int r = 0;
#pragma unroll
        for (int i = 0; i < 8; i++) { int tmp = ws[i]; ws[i] = r; r += tmp; }
        g_bsum[b] = r;
    }
    __syncthreads();
    int off = ws[wid] + (x - tsum);
    if (i0 < NN) {
        g_rowptr[i0] = off;
        if (i0 + 1 < NN) g_rowptr[i0 + 1] = off + v0;
        if (i0 + 2 < NN) g_rowptr[i0 + 2] = off + v0 + v1;
        if (i0 + 3 < NN) g_rowptr[i0 + 3] = off + v0 + v1 + v2;
    }
}

__global__ void k_scan_tops() {
    int lane = threadIdx.x;
    int carry = 0;
    for (int b = 0; b < NBLK; b += 32) {
        int i = b + lane;
        int v = (i < NBLK) ? g_bsum[i] : 0;
        int x = v;
#pragma unroll
        for (int m = 1; m < 32; m <<= 1) {
            int y = __shfl_up_sync(0xffffffffu, x, m);
            if (lane >= m) x += y;
        }
        if (i < NBLK) g_boff[i] = carry + x - v;
        carry += __shfl_sync(0xffffffffu, x, 31);
    }
}

__global__ void k_scatter(const int* __restrict__ rows, const int* __restrict__ cols) {
    int e = blockIdx.x * blockDim.x + threadIdx.x;
    if (e >= EE) return;
    int r = rows[e];
    int pos = g_rowptr[r] + g_boff[r >> 10] + atomicAdd(&g_cnt[r], 1);
    g_csrcol[pos] = cols[e];
}

// ================= split-bf16 HMMA GEMM, 64-row tile, 2 CTA/SM =============
#define ROWB 272
#define SM_AHI  0
#define SM_ALO  (SM_AHI + 64 * ROWB)
#define SM_BHI  (SM_ALO + 64 * ROWB)
#define SM_BLO  (SM_BHI + 128 * ROWB)
#define SM_TOT  (SM_BLO + 128 * ROWB)   // 104448

__device__ __forceinline__ void stage_B_async(uint32_t smb, int t, int widx) {
    const char* bh = reinterpret_cast<const char*>(&g_wt_hi[(size_t)widx * 16384]);
    const char* bl = reinterpret_cast<const char*>(&g_wt_lo[(size_t)widx * 16384]);
#pragma unroll
    for (int i = t; i < 2048; i += 256) {
        uint32_t o = (i >> 4) * ROWB + (i & 15) * 16;
        cp16(smb + SM_BHI + o, bh + i * 16);
        cp16(smb + SM_BLO + o, bl + i * 16);
    }
}

// hmask bit wi: output wi is __half; pmask bit wi: permute cols to head-major
__global__ void __launch_bounds__(256, 2)
k_gemm_tc(const float* __restrict__ A, int M, int nW, int hmask, int pmask,
          int wx0, const float* __restrict__ bias0, float s0, void* __restrict__ C0,
          int wx1, const float* __restrict__ bias1, float s1, void* __restrict__ C1,
          int wx2, const float* __restrict__ bias2, float s2, void* __restrict__ C2) {
    extern __shared__ char sm[];
    const uint32_t smb = smem_u32(sm);
    const int t = threadIdx.x;
    const int wid = t >> 5, lane = t & 31;
    const int mb = wid >> 2, nb = wid & 3;
    const int row0 = blockIdx.x * 64;

    stage_B_async(smb, t, wx0);
    CP_COMMIT();

#pragma unroll
    for (int i = t; i < 2048; i += 256) {
        int r = i >> 5, c4 = i & 31;
        float4 v = make_float4(0.f, 0.f, 0.f, 0.f);
        if (row0 + r < M)
            v = *reinterpret_cast<const float4*>(&A[(size_t)(row0 + r) * 128 + c4 * 4]);
        float h0 = __bfloat162float(__float2bfloat16_rn(v.x));
        float h1 = __bfloat162float(__float2bfloat16_rn(v.y));
        float h2 = __bfloat162float(__float2bfloat16_rn(v.z));
        float h3 = __bfloat162float(__float2bfloat16_rn(v.w));
        uint32_t o = r * ROWB + c4 * 8;
        *reinterpret_cast<uint2*>(sm + SM_AHI + o) =
            make_uint2(pack_bf2(v.x, v.y), pack_bf2(v.z, v.w));
        *reinterpret_cast<uint2*>(sm + SM_ALO + o) =
            make_uint2(pack_bf2(v.x - h0, v.y - h1), pack_bf2(v.z - h2, v.w - h3));
    }
    CP_WAIT0();
    __syncthreads();

    for (int wi = 0; wi < nW; wi++) {
        const float* bias = (wi == 0) ? bias0 : (wi == 1) ? bias1 : bias2;
        float scale       = (wi == 0) ? s0 : (wi == 1) ? s1 : s2;
        void* C           = (wi == 0) ? C0 : (wi == 1) ? C1 : C2;
        const bool ho     = (hmask >> wi) & 1;
        const bool pm     = (pmask >> wi) & 1;

        float acc[2][4][4];
#pragma unroll
        for (int i = 0; i < 2; i++)
#pragma unroll
            for (int j = 0; j < 4; j++)
#pragma unroll
                for (int q = 0; q < 4; q++) acc[i][j][q] = 0.f;

#pragma unroll
        for (int ks = 0; ks < 8; ks++) {
            const int k0 = ks * 16;
            uint32_t ah[2][4], al[2][4];
#pragma unroll
            for (int ms = 0; ms < 2; ms++) {
                int r = mb * 32 + ms * 16 + (lane & 7) + ((lane >> 3) & 1) * 8;
                uint32_t off = r * ROWB + (k0 + (lane >> 4) * 8) * 2;
                ldm_x4(ah[ms][0], ah[ms][1], ah[ms][2], ah[ms][3], smb + SM_AHI + off);
                ldm_x4(al[ms][0], al[ms][1], al[ms][2], al[ms][3], smb + SM_ALO + off);
            }
            uint32_t bh[4][2], bl[4][2];
#pragma unroll
            for (int ng = 0; ng < 2; ng++) {
                int r = nb * 32 + ng * 16 + (lane & 7) + ((lane >= 16) ? 8 : 0);
                uint32_t off = r * ROWB + (k0 + ((lane >> 3) & 1) * 8) * 2;
                uint32_t r0, r1, r2, r3;
                ldm_x4(r0, r1, r2, r3, smb + SM_BHI + off);
                bh[2 * ng][0] = r0; bh[2 * ng][1] = r1;
                bh[2 * ng + 1][0] = r2; bh[2 * ng + 1][1] = r3;
                ldm_x4(r0, r1, r2, r3, smb + SM_BLO + off);
                bl[2 * ng][0] = r0; bl[2 * ng][1] = r1;
                bl[2 * ng + 1][0] = r2; bl[2 * ng + 1][1] = r3;
            }
#pragma unroll
            for (int ms = 0; ms < 2; ms++)
#pragma unroll
                for (int nt = 0; nt < 4; nt++) {
                    mma_bf16(acc[ms][nt], ah[ms], bh[nt][0], bh[nt][1]);
                    mma_bf16(acc[ms][nt], ah[ms], bl[nt][0], bl[nt][1]);
                    mma_bf16(acc[ms][nt], al[ms], bh[nt][0], bh[nt][1]);
                }
        }

        __syncthreads();
        if (wi + 1 < nW) {
            stage_B_async(smb, t, (wi == 0) ? wx1 : wx2);
            CP_COMMIT();
        }

        const int g = lane >> 2, tq = lane & 3;
#pragma unroll
        for (int nt = 0; nt < 4; nt++) {
            int col = nb * 32 + nt * 8 + tq * 2;
            float b0 = __ldg(&bias[col]), b1 = __ldg(&bias[col + 1]);
            // head-major permuted positions for col, col+1
            int p0 = ((col & 7) << 4) | (col >> 3);
            int p1 = (((col + 1) & 7) << 4) | ((col + 1) >> 3);
#pragma unroll
            for (int ms = 0; ms < 2; ms++) {
                int r_lo = row0 + mb * 32 + ms * 16 + g;
#pragma unroll
                for (int hh = 0; hh < 2; hh++) {
                    int r = r_lo + hh * 8;
                    if (r >= M) continue;
                    float o0 = scale * (acc[ms][nt][2 * hh + 0] + b0);
                    float o1 = scale * (acc[ms][nt][2 * hh + 1] + b1);
                    if (!pm) {
                        if (ho) {
                            *reinterpret_cast<__half2*>(
                                &reinterpret_cast<__half*>(C)[(size_t)r * 128 + col]) =
                                __floats2half2_rn(o0, o1);
                        } else {
                            *reinterpret_cast<float2*>(
                                &reinterpret_cast<float*>(C)[(size_t)r * 128 + col]) =
                                make_float2(o0, o1);
                        }
                    } else if (ho) {
                        __half* Ch = reinterpret_cast<__half*>(C);
                        Ch[(size_t)r * 128 + p0] = __float2half_rn(o0);
                        Ch[(size_t)r * 128 + p1] = __float2half_rn(o1);
                    } else {
                        float* Cf = reinterpret_cast<float*>(C);
                        Cf[(size_t)r * 128 + p0] = o0;
                        Cf[(size_t)r * 128 + p1] = o1;
                    }
                }
            }
        }
        if (wi + 1 < nW) {
            CP_WAIT0();
            __syncthreads();
        }
    }
}

// ================= fused per-row attention: head-major, lane=(group,head) ==
// warp per row; lane = (g=lane>>3 edge group, h=lane&7 head). Each lane does
// the full 16-dim dot for its (edge, head) -> 1 expf per (edge,head), no
// shuffle tree. Scores are O(1) so exp without max-shift is exact.
__global__ void __launch_bounds__(256)
k_row(float* __restrict__ out) {
    int w = (blockIdx.x * blockDim.x + threadIdx.x) >> 5;
    if (w >= NN) return;
    const int lane = threadIdx.x & 31;
    const int g = lane >> 3, h = lane & 7;
    const int s = g_rowptr[w] + g_boff[w >> 10];
    const int e = (w + 1 < NN) ? (g_rowptr[w + 1] + g_boff[(w + 1) >> 10]) : EE;

    float qd[16];
    {
        const float4* qp = reinterpret_cast<const float4*>(&g_q[(size_t)w * 128 + h * 16]);
#pragma unroll
        for (int j = 0; j < 4; j++) {
            float4 f = qp[j];
            qd[4 * j] = f.x; qd[4 * j + 1] = f.y;
            qd[4 * j + 2] = f.z; qd[4 * j + 3] = f.w;
        }
    }

    float t = 0.f;
    float acc[16];
#pragma unroll
    for (int j = 0; j < 16; j++) acc[j] = 0.f;

    for (int i = s + g; i < e; i += 8) {   // 2 edges in flight per lane
        int ib = i + 4;
        bool has_b = ib < e;
        int ca = __ldg(&g_csrcol[i]);
        int cb = __ldg(&g_csrcol[has_b ? ib : i]);
        const uint4* kap = reinterpret_cast<const uint4*>(&g_k[(size_t)ca * 128 + h * 16]);
        const uint4* kbp = reinterpret_cast<const uint4*>(&g_k[(size_t)cb * 128 + h * 16]);
        const uint4* vap = reinterpret_cast<const uint4*>(&g_v[(size_t)ca * 128 + h * 16]);
        const uint4* vbp = reinterpret_cast<const uint4*>(&g_v[(size_t)cb * 128 + h * 16]);
        uint4 ka0 = kap[0], ka1 = kap[1];
        uint4 kb0 = kbp[0], kb1 = kbp[1];
        uint4 va0 = vap[0], va1 = vap[1];
        uint4 vb0 = vbp[0], vb1 = vbp[1];

        float da = dot16(qd, ka0, ka1);
        float db = dot16(qd, kb0, kb1);
        float pa = __expf(da);
        float pb = has_b ? __expf(db) : 0.f;
        t += pa + pb;
        acc16(acc, pa, va0, va1);
        acc16(acc, pb, vb0, vb1);
    }

    // combine 4 edge groups (same head lives at lane xor 8, 16)
    t += __shfl_xor_sync(0xffffffffu, t, 8);
    t += __shfl_xor_sync(0xffffffffu, t, 16);
#pragma unroll
    for (int j = 0; j < 16; j++) {
        acc[j] += __shfl_xor_sync(0xffffffffu, acc[j], 8);
        acc[j] += __shfl_xor_sync(0xffffffffu, acc[j], 16);
    }
    float inv = (t > 0.f) ? 1.0f / t : 0.f;

    // out layout [n][d][h]: lane (g,h) writes d = g*4 .. g*4+3
#pragma unroll
    for (int j = 0; j < 4; j++) {
        int d = g * 4 + j;
        out[(size_t)w * 128 + d * 8 + h] = acc[d] * inv;
    }
}

// ================= launch ===================================================
extern "C" void kernel_launch(void* const* d_in, const int* in_sizes, int n_in,
                              void* d_out, int out_size) {
    const float* X    = (const float*)d_in[0];
    const int*   rows = (const int*)d_in[1];
    const int*   cols = (const int*)d_in[2];
    const float* W_in = (const float*)d_in[3];
    const float* b_in = (const float*)d_in[4];
    const float* Wq   = (const float*)d_in[5];
    const float* bq   = (const float*)d_in[6];
    const float* Wk   = (const float*)d_in[7];
    const float* bk   = (const float*)d_in[8];
    const float* Wv   = (const float*)d_in[9];
    const float* bv   = (const float*)d_in[10];
    float* out = (float*)d_out;
    (void)in_sizes; (void)n_in; (void)out_size;

    cudaFuncSetAttribute(k_gemm_tc, cudaFuncAttributeMaxDynamicSharedMemorySize,
                         SM_TOT);

    void *ph, *pq, *pkk, *pv;
    cudaGetSymbolAddress(&ph, g_h);
    cudaGetSymbolAddress(&pq, g_q);
    cudaGetSymbolAddress(&pkk, g_k);
    cudaGetSymbolAddress(&pv, g_v);
    float* h = (float*)ph;

    const int gb = (NN + 63) / 64;

    k_prep<<<391 + 256, 256>>>(W_in, Wq, Wk, Wv);                 // 0
    k_hist<<<(EE + 255) / 256, 256>>>(rows);                       // 1
    k_gemm_tc<<<gb, 256, SM_TOT>>>(X, NN, 1, 0, 0,                 // 2
                                   0, b_in, 1.0f, ph,
                                   0, nullptr, 0.f, nullptr,
                                   0, nullptr, 0.f, nullptr);
    k_gemm_tc<<<gb, 256, SM_TOT>>>(h, NN, 3, 0b110, 0b111,         // 3 (ncu)
                                   1, bq, 0.25f, pq,
                                   2, bk, 1.0f, pkk,
                                   3, bv, 1.0f, pv);
    k_scan_block<<<NBLK, 256>>>();                                 // 4
    k_scan_tops<<<1, 32>>>();                                      // 5
    k_scatter<<<(EE + 255) / 256, 256>>>(rows, cols);              // 6
    k_row<<<(NN * 32 + 255) / 256, 256>>>(out);                    // 7
}

// round 12
// speedup vs baseline: 1.3943x; 1.3943x over previous
#include <cuda_runtime.h>
#include <cuda_bf16.h>
#include <cuda_fp16.h>
#include <cstdint>
#include <math_constants.h>

#define NN 100000
#define EE 1600000
#define NBLK 98

// ---------------- scratch ---------------------------------------------------
__device__ float  g_h[(size_t)NN * 128];   // h canonical; later q head-major
__device__ float  g_q[(size_t)NN * 128];   // q canonical
__device__ __half g_k[(size_t)NN * 128];   // k canonical
__device__ __half g_v[(size_t)NN * 128];   // v canonical
__device__ __half g_k2[(size_t)NN * 128];  // k head-major
__device__ __half g_v2[(size_t)NN * 128];  // v head-major
__device__ int    g_csrcol[EE];
__device__ int    g_rowptr[NN + 1];
__device__ int    g_cnt[NN];
__device__ int    g_bsum[NBLK];
__device__ int    g_boff[NBLK];
__device__ __nv_bfloat16 g_wt_hi[4 * 128 * 128];  // W^T, [w][n][k]
__device__ __nv_bfloat16 g_wt_lo[4 * 128 * 128];

// ---------------- helpers ---------------------------------------------------
__device__ __forceinline__ uint32_t smem_u32(const void* p) {
    uint32_t a;
    asm("{ .reg .u64 t; cvta.to.shared.u64 t, %1; cvt.u32.u64 %0, t; }"
        : "=r"(a) : "l"(p));
    return a;
}
__device__ __forceinline__ void ldm_x4(uint32_t& r0, uint32_t& r1,
                                       uint32_t& r2, uint32_t& r3, uint32_t addr) {
    asm volatile("ldmatrix.sync.aligned.m8n8.x4.shared.b16 {%0,%1,%2,%3}, [%4];"
                 : "=r"(r0), "=r"(r1), "=r"(r2), "=r"(r3) : "r"(addr));
}
__device__ __forceinline__ void mma_bf16(float* c, const uint32_t* a,
                                         uint32_t b0, uint32_t b1) {
    asm volatile(
        "mma.sync.aligned.m16n8k16.row.col.f32.bf16.bf16.f32 "
        "{%0,%1,%2,%3}, {%4,%5,%6,%7}, {%8,%9}, {%0,%1,%2,%3};"
        : "+f"(c[0]), "+f"(c[1]), "+f"(c[2]), "+f"(c[3])
        : "r"(a[0]), "r"(a[1]), "r"(a[2]), "r"(a[3]), "r"(b0), "r"(b1));
}
__device__ __forceinline__ unsigned pack_bf2(float x, float y) {
    __nv_bfloat162 t = __floats2bfloat162_rn(x, y);
    return *reinterpret_cast<unsigned*>(&t);
}
__device__ __forceinline__ void cp16(uint32_t dst, const void* src) {
    asm volatile("cp.async.cg.shared.global [%0], [%1], 16;"
                 :: "r"(dst), "l"(src) : "memory");
}
#define CP_COMMIT() asm volatile("cp.async.commit_group;" ::: "memory")
#define CP_WAIT0()  asm volatile("cp.async.wait_group 0;" ::: "memory")

__device__ __forceinline__ float dot16(const float* qd, uint4 lo, uint4 hi) {
    uint32_t wbuf[8] = {lo.x, lo.y, lo.z, lo.w, hi.x, hi.y, hi.z, hi.w};
    float d = 0.f;
#pragma unroll
    for (int j = 0; j < 8; j++) {
        float2 f = __half22float2(*reinterpret_cast<const __half2*>(&wbuf[j]));
        d = fmaf(qd[2 * j], f.x, d);
        d = fmaf(qd[2 * j + 1], f.y, d);
    }
    return d;
}
__device__ __forceinline__ void acc16(float* acc, float p, uint4 lo, uint4 hi) {
    uint32_t wbuf[8] = {lo.x, lo.y, lo.z, lo.w, hi.x, hi.y, hi.z, hi.w};
#pragma unroll
    for (int j = 0; j < 8; j++) {
        float2 f = __half22float2(*reinterpret_cast<const __half2*>(&wbuf[j]));
        acc[2 * j]     = fmaf(p, f.x, acc[2 * j]);
        acc[2 * j + 1] = fmaf(p, f.y, acc[2 * j + 1]);
    }
}

// ================= prep: zero cnt + transpose/convert weights ===============
__global__ void k_prep(const float* __restrict__ W0, const float* __restrict__ W1,
                       const float* __restrict__ W2, const float* __restrict__ W3) {
    if (blockIdx.x < 391) {
        int i = blockIdx.x * 256 + threadIdx.x;
        if (i < NN) g_cnt[i] = 0;
    } else {
        int j = (blockIdx.x - 391) * 256 + threadIdx.x;  // [0, 65536)
        int w = j >> 14, rem = j & 16383;
        int n = rem >> 7, kk = rem & 127;
        const float* Wp = (w == 0) ? W0 : (w == 1) ? W1 : (w == 2) ? W2 : W3;
        float val = Wp[kk * 128 + n];
        float hi = __bfloat162float(__float2bfloat16_rn(val));
        g_wt_hi[j] = __float2bfloat16_rn(val);
        g_wt_lo[j] = __float2bfloat16_rn(val - hi);
    }
}

// ================= CSR build ===============================================
__global__ void k_hist(const int* __restrict__ rows) {
    int e = blockIdx.x * blockDim.x + threadIdx.x;
    if (e < EE) atomicAdd(&g_cnt[rows[e]], 1);
}

__global__ void __launch_bounds__(256) k_scan_block() {
    __shared__ int ws[8];
    int b = blockIdx.x, t = threadIdx.x;
    int i0 = b * 1024 + t * 4;
    int v0 = 0, v1 = 0, v2 = 0, v3 = 0;
    if (i0 < NN) {
        if (i0 + 3 < NN) {
            int4 vv = *reinterpret_cast<const int4*>(&g_cnt[i0]);
            v0 = vv.x; v1 = vv.y; v2 = vv.z; v3 = vv.w;
            *reinterpret_cast<int4*>(&g_cnt[i0]) = make_int4(0, 0, 0, 0);
        } else {
            v0 = g_cnt[i0]; g_cnt[i0] = 0;
            if (i0 + 1 < NN) { v1 = g_cnt[i0 + 1]; g_cnt[i0 + 1] = 0; }
            if (i0 + 2 < NN) { v2 = g_cnt[i0 + 2]; g_cnt[i0 + 2] = 0; }
        }
    }
    int tsum = v0 + v1 + v2 + v3;
    int lane = t & 31, wid = t >> 5;
    int x = tsum;
#pragma unroll
    for (int m = 1; m < 32; m <<= 1) {
        int y = __shfl_up_sync(0xffffffffu, x, m);
        if (lane >= m) x += y;
    }
    if (lane == 31) ws[wid] = x;
    __syncthreads();
    if (t == 0) {
        int r = 0;
#pragma unroll
        for (int i = 0; i < 8; i++) { int tmp = ws[i]; ws[i] = r; r += tmp; }
        g_bsum[b] = r;
    }
    __syncthreads();
    int off = ws[wid] + (x - tsum);
    if (i0 < NN) {
        g_rowptr[i0] = off;
        if (i0 + 1 < NN) g_rowptr[i0 + 1] = off + v0;
        if (i0 + 2 < NN) g_rowptr[i0 + 2] = off + v0 + v1;
        if (i0 + 3 < NN) g_rowptr[i0 + 3] = off + v0 + v1 + v2;
    }
}

__global__ void k_scan_tops() {
    int lane = threadIdx.x;
    int carry = 0;
    for (int b = 0; b < NBLK; b += 32) {
        int i = b + lane;
        int v = (i < NBLK) ? g_bsum[i] : 0;
        int x = v;
#pragma unroll
        for (int m = 1; m < 32; m <<= 1) {
            int y = __shfl_up_sync(0xffffffffu, x, m);
            if (lane >= m) x += y;
        }
        if (i < NBLK) g_boff[i] = carry + x - v;
        carry += __shfl_sync(0xffffffffu, x, 31);
    }
}

__global__ void k_scatter(const int* __restrict__ rows, const int* __restrict__ cols) {
    int e = blockIdx.x * blockDim.x + threadIdx.x;
    if (e >= EE) return;
    int r = rows[e];
    int pos = g_rowptr[r] + g_boff[r >> 10] + atomicAdd(&g_cnt[r], 1);
    g_csrcol[pos] = cols[e];
}

// ================= split-bf16 HMMA GEMM, 64-row tile, 2 CTA/SM =============
#define ROWB 272
#define SM_AHI  0
#define SM_ALO  (SM_AHI + 64 * ROWB)
#define SM_BHI  (SM_ALO + 64 * ROWB)
#define SM_BLO  (SM_BHI + 128 * ROWB)
#define SM_TOT  (SM_BLO + 128 * ROWB)   // 104448

__device__ __forceinline__ void stage_B_async(uint32_t smb, int t, int widx) {
    const char* bh = reinterpret_cast<const char*>(&g_wt_hi[(size_t)widx * 16384]);
    const char* bl = reinterpret_cast<const char*>(&g_wt_lo[(size_t)widx * 16384]);
#pragma unroll
    for (int i = t; i < 2048; i += 256) {
        uint32_t o = (i >> 4) * ROWB + (i & 15) * 16;
        cp16(smb + SM_BHI + o, bh + i * 16);
        cp16(smb + SM_BLO + o, bl + i * 16);
    }
}

// hmask bit wi: output wi is __half (else float); canonical coalesced stores
__global__ void __launch_bounds__(256, 2)
k_gemm_tc(const float* __restrict__ A, int M, int nW, int hmask,
          int wx0, const float* __restrict__ bias0, float s0, void* __restrict__ C0,
          int wx1, const float* __restrict__ bias1, float s1, void* __restrict__ C1,
          int wx2, const float* __restrict__ bias2, float s2, void* __restrict__ C2) {
    extern __shared__ char sm[];
    const uint32_t smb = smem_u32(sm);
    const int t = threadIdx.x;
    const int wid = t >> 5, lane = t & 31;
    const int mb = wid >> 2, nb = wid & 3;
    const int row0 = blockIdx.x * 64;

    stage_B_async(smb, t, wx0);
    CP_COMMIT();

#pragma unroll
    for (int i = t; i < 2048; i += 256) {
        int r = i >> 5, c4 = i & 31;
        float4 v = make_float4(0.f, 0.f, 0.f, 0.f);
        if (row0 + r < M)
            v = *reinterpret_cast<const float4*>(&A[(size_t)(row0 + r) * 128 + c4 * 4]);
        float h0 = __bfloat162float(__float2bfloat16_rn(v.x));
        float h1 = __bfloat162float(__float2bfloat16_rn(v.y));
        float h2 = __bfloat162float(__float2bfloat16_rn(v.z));
        float h3 = __bfloat162float(__float2bfloat16_rn(v.w));
        uint32_t o = r * ROWB + c4 * 8;
        *reinterpret_cast<uint2*>(sm + SM_AHI + o) =
            make_uint2(pack_bf2(v.x, v.y), pack_bf2(v.z, v.w));
        *reinterpret_cast<uint2*>(sm + SM_ALO + o) =
            make_uint2(pack_bf2(v.x - h0, v.y - h1), pack_bf2(v.z - h2, v.w - h3));
    }
    CP_WAIT0();
    __syncthreads();

    for (int wi = 0; wi < nW; wi++) {
        const float* bias = (wi == 0) ? bias0 : (wi == 1) ? bias1 : bias2;
        float scale       = (wi == 0) ? s0 : (wi == 1) ? s1 : s2;
        void* C           = (wi == 0) ? C0 : (wi == 1) ? C1 : C2;
        const bool ho     = (hmask >> wi) & 1;

        float acc[2][4][4];
#pragma unroll
        for (int i = 0; i < 2; i++)
#pragma unroll
            for (int j = 0; j < 4; j++)
#pragma unroll
                for (int q = 0; q < 4; q++) acc[i][j][q] = 0.f;

#pragma unroll
        for (int ks = 0; ks < 8; ks++) {
            const int k0 = ks * 16;
            uint32_t ah[2][4], al[2][4];
#pragma unroll
            for (int ms = 0; ms < 2; ms++) {
                int r = mb * 32 + ms * 16 + (lane & 7) + ((lane >> 3) & 1) * 8;
                uint32_t off = r * ROWB + (k0 + (lane >> 4) * 8) * 2;
                ldm_x4(ah[ms][0], ah[ms][1], ah[ms][2], ah[ms][3], smb + SM_AHI + off);
                ldm_x4(al[ms][0], al[ms][1], al[ms][2], al[ms][3], smb + SM_ALO + off);
            }
            uint32_t bh[4][2], bl[4][2];
#pragma unroll
            for (int ng = 0; ng < 2; ng++) {
                int r = nb * 32 + ng * 16 + (lane & 7) + ((lane >= 16) ? 8 : 0);
                uint32_t off = r * ROWB + (k0 + ((lane >> 3) & 1) * 8) * 2;
                uint32_t r0, r1, r2, r3;
                ldm_x4(r0, r1, r2, r3, smb + SM_BHI + off);
                bh[2 * ng][0] = r0; bh[2 * ng][1] = r1;
                bh[2 * ng + 1][0] = r2; bh[2 * ng + 1][1] = r3;
                ldm_x4(r0, r1, r2, r3, smb + SM_BLO + off);
                bl[2 * ng][0] = r0; bl[2 * ng][1] = r1;
                bl[2 * ng + 1][0] = r2; bl[2 * ng + 1][1] = r3;
            }
#pragma unroll
            for (int ms = 0; ms < 2; ms++)
#pragma unroll
                for (int nt = 0; nt < 4; nt++) {
                    mma_bf16(acc[ms][nt], ah[ms], bh[nt][0], bh[nt][1]);
                    mma_bf16(acc[ms][nt], ah[ms], bl[nt][0], bl[nt][1]);
                    mma_bf16(acc[ms][nt], al[ms], bh[nt][0], bh[nt][1]);
                }
        }

        __syncthreads();
        if (wi + 1 < nW) {
            stage_B_async(smb, t, (wi == 0) ? wx1 : wx2);
            CP_COMMIT();
        }

        const int g = lane >> 2, tq = lane & 3;
#pragma unroll
        for (int nt = 0; nt < 4; nt++) {
            int col = nb * 32 + nt * 8 + tq * 2;
            float b0 = __ldg(&bias[col]), b1 = __ldg(&bias[col + 1]);
#pragma unroll
            for (int ms = 0; ms < 2; ms++) {
                int r_lo = row0 + mb * 32 + ms * 16 + g;
#pragma unroll
                for (int hh = 0; hh < 2; hh++) {
                    int r = r_lo + hh * 8;
                    if (r >= M) continue;
                    float o0 = scale * (acc[ms][nt][2 * hh + 0] + b0);
                    float o1 = scale * (acc[ms][nt][2 * hh + 1] + b1);
                    if (ho) {
                        *reinterpret_cast<__half2*>(
                            &reinterpret_cast<__half*>(C)[(size_t)r * 128 + col]) =
                            __floats2half2_rn(o0, o1);
                    } else {
                        *reinterpret_cast<float2*>(
                            &reinterpret_cast<float*>(C)[(size_t)r * 128 + col]) =
                            make_float2(o0, o1);
                    }
                }
            }
        }
        if (wi + 1 < nW) {
            CP_WAIT0();
            __syncthreads();
        }
    }
}

// ================= permute q/k/v to head-major via smem ====================
// canonical col c -> head-major p = (c%8)*16 + c/8;  inverse c = (p%16)*8+p/16.
// 32 node rows per block; q: g_q(f32)->g_h; k: g_k->g_k2; v: g_v->g_v2.
#define PBLK 3125   // NN/32
__global__ void __launch_bounds__(256) k_perm() {
    __shared__ __align__(16) char smraw[16896];
    const int t = threadIdx.x;
    const int tensor = blockIdx.x / PBLK;
    const int row0 = (blockIdx.x - tensor * PBLK) * 32;
    const int r = t >> 3, h = t & 7;

    if (tensor == 0) {
        float (*smf)[132] = reinterpret_cast<float(*)[132]>(smraw);
        const float4* src = reinterpret_cast<const float4*>(&g_q[(size_t)row0 * 128]);
#pragma unroll
        for (int j = 0; j < 4; j++) {
            int i = t + 256 * j;               // 1024 float4 = 32 rows x 32
            float4 v = src[i];
            *reinterpret_cast<float4*>(&smf[i >> 5][(i & 31) * 4]) = v;
        }
        __syncthreads();
        float buf[16];
#pragma unroll
        for (int m = 0; m < 16; m++) buf[m] = smf[r][m * 8 + h];
        float4* dst = reinterpret_cast<float4*>(&g_h[(size_t)(row0 + r) * 128 + h * 16]);
#pragma unroll
        for (int j = 0; j < 4; j++)
            dst[j] = make_float4(buf[4 * j], buf[4 * j + 1], buf[4 * j + 2], buf[4 * j + 3]);
    } else {
        __half (*smh)[136] = reinterpret_cast<__half(*)[136]>(smraw);
        const __half* srcg = (tensor == 1) ? g_k : g_v;
        __half* dstg = (tensor == 1) ? g_k2 : g_v2;
        const uint4* src = reinterpret_cast<const uint4*>(&srcg[(size_t)row0 * 128]);
#pragma unroll
        for (int j = 0; j < 2; j++) {
            int i = t + 256 * j;               // 512 uint4 = 32 rows x 16
            uint4 v = src[i];
            *reinterpret_cast<uint4*>(&smh[i >> 4][(i & 15) * 8]) = v;
        }
        __syncthreads();
        __align__(16) __half buf[16];
#pragma unroll
        for (int m = 0; m < 16; m++) buf[m] = smh[r][m * 8 + h];
        uint4* dst = reinterpret_cast<uint4*>(&dstg[(size_t)(row0 + r) * 128 + h * 16]);
        dst[0] = reinterpret_cast<uint4*>(buf)[0];
        dst[1] = reinterpret_cast<uint4*>(buf)[1];
    }
}

// ================= fused per-row attention: head-major, lane=(group,head) ==
__global__ void __launch_bounds__(256)
k_row(float* __restrict__ out) {
    int w = (blockIdx.x * blockDim.x + threadIdx.x) >> 5;
    if (w >= NN) return;
    const int lane = threadIdx.x & 31;
    const int g = lane >> 3, h = lane & 7;
    const int s = g_rowptr[w] + g_boff[w >> 10];
    const int e = (w + 1 < NN) ? (g_rowptr[w + 1] + g_boff[(w + 1) >> 10]) : EE;

    float qd[16];
    {
        const float4* qp = reinterpret_cast<const float4*>(&g_h[(size_t)w * 128 + h * 16]);
#pragma unroll
        for (int j = 0; j < 4; j++) {
            float4 f = qp[j];
            qd[4 * j] = f.x; qd[4 * j + 1] = f.y;
            qd[4 * j + 2] = f.z; qd[4 * j + 3] = f.w;
        }
    }

    float t = 0.f;
    float acc[16];
#pragma unroll
    for (int j = 0; j < 16; j++) acc[j] = 0.f;

    for (int i = s + g; i < e; i += 8) {   // 2 edges in flight per lane
        int ib = i + 4;
        bool has_b = ib < e;
        int ca = __ldg(&g_csrcol[i]);
        int cb = __ldg(&g_csrcol[has_b ? ib : i]);
        const uint4* kap = reinterpret_cast<const uint4*>(&g_k2[(size_t)ca * 128 + h * 16]);
        const uint4* kbp = reinterpret_cast<const uint4*>(&g_k2[(size_t)cb * 128 + h * 16]);
        const uint4* vap = reinterpret_cast<const uint4*>(&g_v2[(size_t)ca * 128 + h * 16]);
        const uint4* vbp = reinterpret_cast<const uint4*>(&g_v2[(size_t)cb * 128 + h * 16]);
        uint4 ka0 = kap[0], ka1 = kap[1];
        uint4 kb0 = kbp[0], kb1 = kbp[1];
        uint4 va0 = vap[0], va1 = vap[1];
        uint4 vb0 = vbp[0], vb1 = vbp[1];

        float da = dot16(qd, ka0, ka1);
        float db = dot16(qd, kb0, kb1);
        float pa = __expf(da);
        float pb = has_b ? __expf(db) : 0.f;
        t += pa + pb;
        acc16(acc, pa, va0, va1);
        acc16(acc, pb, vb0, vb1);
    }

    t += __shfl_xor_sync(0xffffffffu, t, 8);
    t += __shfl_xor_sync(0xffffffffu, t, 16);
#pragma unroll
    for (int j = 0; j < 16; j++) {
        acc[j] += __shfl_xor_sync(0xffffffffu, acc[j], 8);
        acc[j] += __shfl_xor_sync(0xffffffffu, acc[j], 16);
    }
    float inv = (t > 0.f) ? 1.0f / t : 0.f;

    // out layout [n][d][h]: lane (g,h) writes d = g*4 .. g*4+3
#pragma unroll
    for (int j = 0; j < 4; j++) {
        int d = g * 4 + j;
        out[(size_t)w * 128 + d * 8 + h] = acc[d] * inv;
    }
}

// ================= launch ===================================================
extern "C" void kernel_launch(void* const* d_in, const int* in_sizes, int n_in,
                              void* d_out, int out_size) {
    const float* X    = (const float*)d_in[0];
    const int*   rows = (const int*)d_in[1];
    const int*   cols = (const int*)d_in[2];
    const float* W_in = (const float*)d_in[3];
    const float* b_in = (const float*)d_in[4];
    const float* Wq   = (const float*)d_in[5];
    const float* bq   = (const float*)d_in[6];
    const float* Wk   = (const float*)d_in[7];
    const float* bk   = (const float*)d_in[8];
    const float* Wv   = (const float*)d_in[9];
    const float* bv   = (const float*)d_in[10];
    float* out = (float*)d_out;
    (void)in_sizes; (void)n_in; (void)out_size;

    cudaFuncSetAttribute(k_gemm_tc, cudaFuncAttributeMaxDynamicSharedMemorySize,
                         SM_TOT);

    void *ph, *pq, *pkk, *pv;
    cudaGetSymbolAddress(&ph, g_h);
    cudaGetSymbolAddress(&pq, g_q);
    cudaGetSymbolAddress(&pkk, g_k);
    cudaGetSymbolAddress(&pv, g_v);
    float* h = (float*)ph;

    const int gb = (NN + 63) / 64;

    k_prep<<<391 + 256, 256>>>(W_in, Wq, Wk, Wv);                 // 0
    k_hist<<<(EE + 255) / 256, 256>>>(rows);                       // 1
    k_gemm_tc<<<gb, 256, SM_TOT>>>(X, NN, 1, 0,                    // 2
                                   0, b_in, 1.0f, ph,
                                   0, nullptr, 0.f, nullptr,
                                   0, nullptr, 0.f, nullptr);
    k_gemm_tc<<<gb, 256, SM_TOT>>>(h, NN, 3, 0b110,                // 3 (ncu)
                                   1, bq, 0.25f, pq,
                                   2, bk, 1.0f, pkk,
                                   3, bv, 1.0f, pv);
    k_perm<<<3 * PBLK, 256>>>();                                   // 4
    k_scan_block<<<NBLK, 256>>>();                                 // 5
    k_scan_tops<<<1, 32>>>();                                      // 6
    k_scatter<<<(EE + 255) / 256, 256>>>(rows, cols);              // 7
    k_row<<<(NN * 32 + 255) / 256, 256>>>(out);                    // 8
}

// round 13
// speedup vs baseline: 1.5934x; 1.1428x over previous
#include <cuda_runtime.h>
#include <cuda_bf16.h>
#include <cuda_fp16.h>
#include <cstdint>
#include <math_constants.h>

#define NN 100000
#define EE 1600000
#define NBLK 98

// ---------------- scratch ---------------------------------------------------
__device__ float  g_q[(size_t)NN * 128];   // q canonical (scaled)
__device__ __half g_k[(size_t)NN * 128];   // k canonical
__device__ __half g_v[(size_t)NN * 128];   // v canonical
__device__ __half g_k2[(size_t)NN * 128];  // k head-major
__device__ __half g_v2[(size_t)NN * 128];  // v head-major
__device__ int    g_csrcol[EE];
__device__ int    g_rowptr[NN + 1];
__device__ int    g_cnt[NN];
__device__ int    g_bsum[NBLK];
__device__ int    g_boff[NBLK];
__device__ int    g_tick;
__device__ __nv_bfloat16 g_wt_hi[4 * 128 * 128];  // W^T, [w][n][k]
__device__ __nv_bfloat16 g_wt_lo[4 * 128 * 128];

// ---------------- helpers ---------------------------------------------------
__device__ __forceinline__ uint32_t smem_u32(const void* p) {
    uint32_t a;
    asm("{ .reg .u64 t; cvta.to.shared.u64 t, %1; cvt.u32.u64 %0, t; }"
        : "=r"(a) : "l"(p));
    return a;
}
__device__ __forceinline__ void ldm_x4(uint32_t& r0, uint32_t& r1,
                                       uint32_t& r2, uint32_t& r3, uint32_t addr) {
    asm volatile("ldmatrix.sync.aligned.m8n8.x4.shared.b16 {%0,%1,%2,%3}, [%4];"
                 : "=r"(r0), "=r"(r1), "=r"(r2), "=r"(r3) : "r"(addr));
}
__device__ __forceinline__ void mma_bf16(float* c, const uint32_t* a,
                                         uint32_t b0, uint32_t b1) {
    asm volatile(
        "mma.sync.aligned.m16n8k16.row.col.f32.bf16.bf16.f32 "
        "{%0,%1,%2,%3}, {%4,%5,%6,%7}, {%8,%9}, {%0,%1,%2,%3};"
        : "+f"(c[0]), "+f"(c[1]), "+f"(c[2]), "+f"(c[3])
        : "r"(a[0]), "r"(a[1]), "r"(a[2]), "r"(a[3]), "r"(b0), "r"(b1));
}
__device__ __forceinline__ unsigned pack_bf2(float x, float y) {
    __nv_bfloat162 t = __floats2bfloat162_rn(x, y);
    return *reinterpret_cast<unsigned*>(&t);
}
__device__ __forceinline__ void cp16(uint32_t dst, const void* src) {
    asm volatile("cp.async.cg.shared.global [%0], [%1], 16;"
                 :: "r"(dst), "l"(src) : "memory");
}
#define CP_COMMIT() asm volatile("cp.async.commit_group;" ::: "memory")
#define CP_WAIT0()  asm volatile("cp.async.wait_group 0;" ::: "memory")

__device__ __forceinline__ float dot16(const float* qd, uint4 lo, uint4 hi) {
    uint32_t wbuf[8] = {lo.x, lo.y, lo.z, lo.w, hi.x, hi.y, hi.z, hi.w};
    float d = 0.f;
#pragma unroll
    for (int j = 0; j < 8; j++) {
        float2 f = __half22float2(*reinterpret_cast<const __half2*>(&wbuf[j]));
        d = fmaf(qd[2 * j], f.x, d);
        d = fmaf(qd[2 * j + 1], f.y, d);
    }
    return d;
}
__device__ __forceinline__ void acc16(float* acc, float p, uint4 lo, uint4 hi) {
    uint32_t wbuf[8] = {lo.x, lo.y, lo.z, lo.w, hi.x, hi.y, hi.z, hi.w};
#pragma unroll
    for (int j = 0; j < 8; j++) {
        float2 f = __half22float2(*reinterpret_cast<const __half2*>(&wbuf[j]));
        acc[2 * j]     = fmaf(p, f.x, acc[2 * j]);
        acc[2 * j + 1] = fmaf(p, f.y, acc[2 * j + 1]);
    }
}

// ================= prep: transpose/convert weights =========================
__global__ void k_prep(const float* __restrict__ W0, const float* __restrict__ W1,
                       const float* __restrict__ W2, const float* __restrict__ W3) {
    int j = blockIdx.x * 256 + threadIdx.x;  // [0, 65536)
    int w = j >> 14, rem = j & 16383;
    int n = rem >> 7, kk = rem & 127;
    const float* Wp = (w == 0) ? W0 : (w == 1) ? W1 : (w == 2) ? W2 : W3;
    float val = Wp[kk * 128 + n];
    float hi = __bfloat162float(__float2bfloat16_rn(val));
    g_wt_hi[j] = __float2bfloat16_rn(val);
    g_wt_lo[j] = __float2bfloat16_rn(val - hi);
}

// ================= CSR build ===============================================
// g_cnt is zero on entry: bss-zero on first call, re-zeroed by k_row since.
__global__ void k_hist(const int* __restrict__ rows) {
    int e = blockIdx.x * blockDim.x + threadIdx.x;
    if (e < EE) atomicAdd(&g_cnt[rows[e]], 1);
}

// block-local exclusive scan + zero cnt; last block scans block sums -> boff
__global__ void __launch_bounds__(256) k_scan_block() {
    __shared__ int ws[8];
    __shared__ int islast;
    int b = blockIdx.x, t = threadIdx.x;
    int i0 = b * 1024 + t * 4;
    int v0 = 0, v1 = 0, v2 = 0, v3 = 0;
    if (i0 < NN) {
        if (i0 + 3 < NN) {
            int4 vv = *reinterpret_cast<const int4*>(&g_cnt[i0]);
            v0 = vv.x; v1 = vv.y; v2 = vv.z; v3 = vv.w;
            *reinterpret_cast<int4*>(&g_cnt[i0]) = make_int4(0, 0, 0, 0);
        } else {
            v0 = g_cnt[i0]; g_cnt[i0] = 0;
            if (i0 + 1 < NN) { v1 = g_cnt[i0 + 1]; g_cnt[i0 + 1] = 0; }
            if (i0 + 2 < NN) { v2 = g_cnt[i0 + 2]; g_cnt[i0 + 2] = 0; }
        }
    }
    int tsum = v0 + v1 + v2 + v3;
    int lane = t & 31, wid = t >> 5;
    int x = tsum;
#pragma unroll
    for (int m = 1; m < 32; m <<= 1) {
        int y = __shfl_up_sync(0xffffffffu, x, m);
        if (lane >= m) x += y;
    }
    if (lane == 31) ws[wid] = x;
    __syncthreads();
    if (t == 0) {
        int r = 0;
#pragma unroll
        for (int i = 0; i < 8; i++) { int tmp = ws[i]; ws[i] = r; r += tmp; }
        g_bsum[b] = r;
    }
    __syncthreads();
    int off = ws[wid] + (x - tsum);
    if (i0 < NN) {
        g_rowptr[i0] = off;
        if (i0 + 1 < NN) g_rowptr[i0 + 1] = off + v0;
        if (i0 + 2 < NN) g_rowptr[i0 + 2] = off + v0 + v1;
        if (i0 + 3 < NN) g_rowptr[i0 + 3] = off + v0 + v1 + v2;
    }

    // ---- last arriving block scans the NBLK block sums ----
    if (t == 0) {
        __threadfence();
        int old = atomicAdd(&g_tick, 1);
        islast = (old == NBLK - 1) ? 1 : 0;
        if (islast) g_tick = 0;          // reset for next replay
    }
    __syncthreads();
    if (islast && t < 32) {
        __threadfence();
        int carry = 0;
        for (int bb = 0; bb < NBLK; bb += 32) {
            int i = bb + t;
            int v = (i < NBLK) ? g_bsum[i] : 0;
            int xx = v;
#pragma unroll
            for (int m = 1; m < 32; m <<= 1) {
                int y = __shfl_up_sync(0xffffffffu, xx, m);
                if (t >= m) xx += y;
            }
            if (i < NBLK) g_boff[i] = carry + xx - v;
            carry += __shfl_sync(0xffffffffu, xx, 31);
        }
    }
}

__global__ void k_scatter(const int* __restrict__ rows, const int* __restrict__ cols) {
    int e = blockIdx.x * blockDim.x + threadIdx.x;
    if (e >= EE) return;
    int r = rows[e];
    int pos = g_rowptr[r] + g_boff[r >> 10] + atomicAdd(&g_cnt[r], 1);
    g_csrcol[pos] = cols[e];
}

// ================= fused split-bf16 HMMA GEMM: X->h->{q,k,v} ===============
// 64-row tile, 2 CTA/SM. h epilogue converts acc -> bf16 hi/lo INTO the A
// smem tile (no global h), then Wq/Wk/Wv cycle through the B buffers.
#define ROWB 272
#define SM_AHI  0
#define SM_ALO  (SM_AHI + 64 * ROWB)
#define SM_BHI  (SM_ALO + 64 * ROWB)
#define SM_BLO  (SM_BHI + 128 * ROWB)
#define SM_TOT  (SM_BLO + 128 * ROWB)   // 104448

__device__ __forceinline__ void stage_B_async(uint32_t smb, int t, int widx) {
    const char* bh = reinterpret_cast<const char*>(&g_wt_hi[(size_t)widx * 16384]);
    const char* bl = reinterpret_cast<const char*>(&g_wt_lo[(size_t)widx * 16384]);
#pragma unroll
    for (int i = t; i < 2048; i += 256) {
        uint32_t o = (i >> 4) * ROWB + (i & 15) * 16;
        cp16(smb + SM_BHI + o, bh + i * 16);
        cp16(smb + SM_BLO + o, bl + i * 16);
    }
}

__global__ void __launch_bounds__(256, 2)
k_gemm_fused(const float* __restrict__ X, int M,
             const float* __restrict__ b_in, const float* __restrict__ bq,
             const float* __restrict__ bk, const float* __restrict__ bv,
             float* __restrict__ qo, __half* __restrict__ ko,
             __half* __restrict__ vo) {
    extern __shared__ char sm[];
    const uint32_t smb = smem_u32(sm);
    const int t = threadIdx.x;
    const int wid = t >> 5, lane = t & 31;
    const int mb = wid >> 2, nb = wid & 3;
    const int row0 = blockIdx.x * 64;

    stage_B_async(smb, t, 0);   // W_in
    CP_COMMIT();

    // ---- stage A = X (fp32 -> bf16 hi/lo) ----
#pragma unroll
    for (int i = t; i < 2048; i += 256) {
        int r = i >> 5, c4 = i & 31;
        float4 v = make_float4(0.f, 0.f, 0.f, 0.f);
        if (row0 + r < M)
            v = *reinterpret_cast<const float4*>(&X[(size_t)(row0 + r) * 128 + c4 * 4]);
        float h0 = __bfloat162float(__float2bfloat16_rn(v.x));
        float h1 = __bfloat162float(__float2bfloat16_rn(v.y));
        float h2 = __bfloat162float(__float2bfloat16_rn(v.z));
        float h3 = __bfloat162float(__float2bfloat16_rn(v.w));
        uint32_t o = r * ROWB + c4 * 8;
        *reinterpret_cast<uint2*>(sm + SM_AHI + o) =
            make_uint2(pack_bf2(v.x, v.y), pack_bf2(v.z, v.w));
        *reinterpret_cast<uint2*>(sm + SM_ALO + o) =
            make_uint2(pack_bf2(v.x - h0, v.y - h1), pack_bf2(v.z - h2, v.w - h3));
    }
    CP_WAIT0();
    __syncthreads();

#pragma unroll 1
    for (int wi = 0; wi < 4; wi++) {
        const float* bias = (wi == 0) ? b_in : (wi == 1) ? bq : (wi == 2) ? bk : bv;

        float acc[2][4][4];
#pragma unroll
        for (int i = 0; i < 2; i++)
#pragma unroll
            for (int j = 0; j < 4; j++)
#pragma unroll
                for (int q = 0; q < 4; q++) acc[i][j][q] = 0.f;

#pragma unroll
        for (int ks = 0; ks < 8; ks++) {
            const int k0 = ks * 16;
            uint32_t ah[2][4], al[2][4];
#pragma unroll
            for (int ms = 0; ms < 2; ms++) {
                int r = mb * 32 + ms * 16 + (lane & 7) + ((lane >> 3) & 1) * 8;
                uint32_t off = r * ROWB + (k0 + (lane >> 4) * 8) * 2;
                ldm_x4(ah[ms][0], ah[ms][1], ah[ms][2], ah[ms][3], smb + SM_AHI + off);
                ldm_x4(al[ms][0], al[ms][1], al[ms][2], al[ms][3], smb + SM_ALO + off);
            }
            uint32_t bh[4][2], bl[4][2];
#pragma unroll
            for (int ng = 0; ng < 2; ng++) {
                int r = nb * 32 + ng * 16 + (lane & 7) + ((lane >= 16) ? 8 : 0);
                uint32_t off = r * ROWB + (k0 + ((lane >> 3) & 1) * 8) * 2;
                uint32_t r0, r1, r2, r3;
                ldm_x4(r0, r1, r2, r3, smb + SM_BHI + off);
                bh[2 * ng][0] = r0; bh[2 * ng][1] = r1;
                bh[2 * ng + 1][0] = r2; bh[2 * ng + 1][1] = r3;
                ldm_x4(r0, r1, r2, r3, smb + SM_BLO + off);
                bl[2 * ng][0] = r0; bl[2 * ng][1] = r1;
                bl[2 * ng + 1][0] = r2; bl[2 * ng + 1][1] = r3;
            }
#pragma unroll
            for (int ms = 0; ms < 2; ms++)
#pragma unroll
                for (int nt = 0; nt < 4; nt++) {
                    mma_bf16(acc[ms][nt], ah[ms], bh[nt][0], bh[nt][1]);
                    mma_bf16(acc[ms][nt], ah[ms], bl[nt][0], bl[nt][1]);
                    mma_bf16(acc[ms][nt], al[ms], bh[nt][0], bh[nt][1]);
                }
        }

        __syncthreads();   // all warps done reading A and B smem
        if (wi < 3) {
            stage_B_async(smb, t, wi + 1);
            CP_COMMIT();
        }

        // ---- epilogue ----
        const int g = lane >> 2, tq = lane & 3;
#pragma unroll
        for (int nt = 0; nt < 4; nt++) {
            int col = nb * 32 + nt * 8 + tq * 2;
            float b0 = __ldg(&bias[col]), b1 = __ldg(&bias[col + 1]);
#pragma unroll
            for (int ms = 0; ms < 2; ms++) {
#pragma unroll
                for (int hh = 0; hh < 2; hh++) {
                    int rl = mb * 32 + ms * 16 + g + hh * 8;  // local row
                    float o0 = acc[ms][nt][2 * hh + 0] + b0;
                    float o1 = acc[ms][nt][2 * hh + 1] + b1;
                    if (wi == 0) {
                        // h -> bf16 hi/lo back into the A smem tile
                        float f0 = __bfloat162float(__float2bfloat16_rn(o0));
                        float f1 = __bfloat162float(__float2bfloat16_rn(o1));
                        uint32_t o = rl * ROWB + col * 2;
                        *reinterpret_cast<uint32_t*>(sm + SM_AHI + o) = pack_bf2(o0, o1);
                        *reinterpret_cast<uint32_t*>(sm + SM_ALO + o) =
                            pack_bf2(o0 - f0, o1 - f1);
                    } else {
                        int r = row0 + rl;
                        if (r < M) {
                            if (wi == 1) {
                                *reinterpret_cast<float2*>(&qo[(size_t)r * 128 + col]) =
                                    make_float2(0.25f * o0, 0.25f * o1);
                            } else {
                                __half* C = (wi == 2) ? ko : vo;
                                *reinterpret_cast<__half2*>(&C[(size_t)r * 128 + col]) =
                                    __floats2half2_rn(o0, o1);
                            }
                        }
                    }
                }
            }
        }
        if (wi < 3) {
            CP_WAIT0();
            __syncthreads();   // As rewrite (wi=0) + next B visible to all
        }
    }
}

// ================= permute k/v to head-major via smem ======================
// canonical col c -> head-major p = (c%8)*16 + c/8
#define PBLK 3125   // NN/32
__global__ void __launch_bounds__(256) k_perm() {
    __shared__ __align__(16) __half smh[32][136];
    const int t = threadIdx.x;
    const int tensor = blockIdx.x / PBLK;
    const int row0 = (blockIdx.x - tensor * PBLK) * 32;
    const int r = t >> 3, h = t & 7;

    const __half* srcg = (tensor == 0) ? g_k : g_v;
    __half* dstg = (tensor == 0) ? g_k2 : g_v2;
    const uint4* src = reinterpret_cast<const uint4*>(&srcg[(size_t)row0 * 128]);
#pragma unroll
    for (int j = 0; j < 2; j++) {
        int i = t + 256 * j;               // 512 uint4 = 32 rows x 16
        uint4 v = src[i];
        *reinterpret_cast<uint4*>(&smh[i >> 4][(i & 15) * 8]) = v;
    }
    __syncthreads();
    __align__(16) __half buf[16];
#pragma unroll
    for (int m = 0; m < 16; m++) buf[m] = smh[r][m * 8 + h];
    uint4* dst = reinterpret_cast<uint4*>(&dstg[(size_t)(row0 + r) * 128 + h * 16]);
    dst[0] = reinterpret_cast<uint4*>(buf)[0];
    dst[1] = reinterpret_cast<uint4*>(buf)[1];
}

// ================= fused per-row attention: head-major, lane=(group,head) ==
__global__ void __launch_bounds__(256)
k_row(float* __restrict__ out) {
    int w = (blockIdx.x * blockDim.x + threadIdx.x) >> 5;
    if (w >= NN) return;
    const int lane = threadIdx.x & 31;
    const int g = lane >> 3, h = lane & 7;
    const int s = g_rowptr[w] + g_boff[w >> 10];
    const int e = (w + 1 < NN) ? (g_rowptr[w + 1] + g_boff[(w + 1) >> 10]) : EE;

    if (lane == 0) g_cnt[w] = 0;   // reset for next run's k_hist

    float qd[16];   // strided head-major view of canonical q (lanes broadcast)
#pragma unroll
    for (int j = 0; j < 16; j++)
        qd[j] = __ldg(&g_q[(size_t)w * 128 + j * 8 + h]);

    float t = 0.f;
    float acc[16];
#pragma unroll
    for (int j = 0; j < 16; j++) acc[j] = 0.f;

    for (int i = s + g; i < e; i += 8) {   // 2 edges in flight per lane
        int ib = i + 4;
        bool has_b = ib < e;
        int ca = __ldg(&g_csrcol[i]);
        int cb = __ldg(&g_csrcol[has_b ? ib : i]);
        const uint4* kap = reinterpret_cast<const uint4*>(&g_k2[(size_t)ca * 128 + h * 16]);
        const uint4* kbp = reinterpret_cast<const uint4*>(&g_k2[(size_t)cb * 128 + h * 16]);
        const uint4* vap = reinterpret_cast<const uint4*>(&g_v2[(size_t)ca * 128 + h * 16]);
        const uint4* vbp = reinterpret_cast<const uint4*>(&g_v2[(size_t)cb * 128 + h * 16]);
        uint4 ka0 = kap[0], ka1 = kap[1];
        uint4 kb0 = kbp[0], kb1 = kbp[1];
        uint4 va0 = vap[0], va1 = vap[1];
        uint4 vb0 = vbp[0], vb1 = vbp[1];

        float da = dot16(qd, ka0, ka1);
        float db = dot16(qd, kb0, kb1);
        float pa = __expf(da);
        float pb = has_b ? __expf(db) : 0.f;
        t += pa + pb;
        acc16(acc, pa, va0, va1);
        acc16(acc, pb, vb0, vb1);
    }

    t += __shfl_xor_sync(0xffffffffu, t, 8);
    t += __shfl_xor_sync(0xffffffffu, t, 16);
#pragma unroll
    for (int j = 0; j < 16; j++) {
        acc[j] += __shfl_xor_sync(0xffffffffu, acc[j], 8);
        acc[j] += __shfl_xor_sync(0xffffffffu, acc[j], 16);
    }
    float inv = (t > 0.f) ? 1.0f / t : 0.f;

    // out layout [n][d][h]: lane (g,h) writes d = g*4 .. g*4+3
#pragma unroll
    for (int j = 0; j < 4; j++) {
        int d = g * 4 + j;
        out[(size_t)w * 128 + d * 8 + h] = acc[d] * inv;
    }
}

// ================= launch ===================================================
extern "C" void kernel_launch(void* const* d_in, const int* in_sizes, int n_in,
                              void* d_out, int out_size) {
    const float* X    = (const float*)d_in[0];
    const int*   rows = (const int*)d_in[1];
    const int*   cols = (const int*)d_in[2];
    const float* W_in = (const float*)d_in[3];
    const float* b_in = (const float*)d_in[4];
    const float* Wq   = (const float*)d_in[5];
    const float* bq   = (const float*)d_in[6];
    const float* Wk   = (const float*)d_in[7];
    const float* bk   = (const float*)d_in[8];
    const float* Wv   = (const float*)d_in[9];
    const float* bv   = (const float*)d_in[10];
    float* out = (float*)d_out;
    (void)in_sizes; (void)n_in; (void)out_size;

    cudaFuncSetAttribute(k_gemm_fused, cudaFuncAttributeMaxDynamicSharedMemorySize,
                         SM_TOT);

    void *pq, *pkk, *pv;
    cudaGetSymbolAddress(&pq, g_q);
    cudaGetSymbolAddress(&pkk, g_k);
    cudaGetSymbolAddress(&pv, g_v);

    const int gb = (NN + 63) / 64;

    k_hist<<<(EE + 255) / 256, 256>>>(rows);                       // 0
    k_prep<<<256, 256>>>(W_in, Wq, Wk, Wv);                        // 1
    k_scan_block<<<NBLK, 256>>>();                                 // 2 (+tops)
    k_gemm_fused<<<gb, 256, SM_TOT>>>(X, NN, b_in, bq, bk, bv,     // 3 (ncu)
                                      (float*)pq, (__half*)pkk, (__half*)pv);
    k_perm<<<2 * PBLK, 256>>>();                                   // 4
    k_scatter<<<(EE + 255) / 256, 256>>>(rows, cols);              // 5
    k_row<<<(NN * 32 + 255) / 256, 256>>>(out);                    // 6
}

// round 14
// speedup vs baseline: 1.5976x; 1.0026x over previous
#include <cuda_runtime.h>
#include <cuda_bf16.h>
#include <cuda_fp16.h>
#include <cstdint>
#include <math_constants.h>

#define NN 100000
#define EE 1600000
#define NBLK 98

// ---------------- scratch ---------------------------------------------------
__device__ float  g_q[(size_t)NN * 128];   // q canonical (scaled)
__device__ __half g_k[(size_t)NN * 128];   // k canonical
__device__ __half g_v[(size_t)NN * 128];   // v canonical
__device__ __half g_k2[(size_t)NN * 128];  // k head-major
__device__ __half g_v2[(size_t)NN * 128];  // v head-major
__device__ int    g_csrcol[EE];
__device__ int    g_rowptr[NN + 1];
__device__ int    g_cnt[NN];
__device__ int    g_bsum[NBLK];
__device__ int    g_boff[NBLK];
__device__ int    g_tick;
__device__ __nv_bfloat16 g_wt_hi[4 * 128 * 128];  // W^T, [w][n][k]
__device__ __nv_bfloat16 g_wt_lo[4 * 128 * 128];

// ---------------- helpers ---------------------------------------------------
__device__ __forceinline__ uint32_t smem_u32(const void* p) {
    uint32_t a;
    asm("{ .reg .u64 t; cvta.to.shared.u64 t, %1; cvt.u32.u64 %0, t; }"
        : "=r"(a) : "l"(p));
    return a;
}
__device__ __forceinline__ void ldm_x4(uint32_t& r0, uint32_t& r1,
                                       uint32_t& r2, uint32_t& r3, uint32_t addr) {
    asm volatile("ldmatrix.sync.aligned.m8n8.x4.shared.b16 {%0,%1,%2,%3}, [%4];"
                 : "=r"(r0), "=r"(r1), "=r"(r2), "=r"(r3) : "r"(addr));
}
__device__ __forceinline__ void mma_bf16(float* c, const uint32_t* a,
                                         uint32_t b0, uint32_t b1) {
    asm volatile(
        "mma.sync.aligned.m16n8k16.row.col.f32.bf16.bf16.f32 "
        "{%0,%1,%2,%3}, {%4,%5,%6,%7}, {%8,%9}, {%0,%1,%2,%3};"
        : "+f"(c[0]), "+f"(c[1]), "+f"(c[2]), "+f"(c[3])
        : "r"(a[0]), "r"(a[1]), "r"(a[2]), "r"(a[3]), "r"(b0), "r"(b1));
}
__device__ __forceinline__ unsigned pack_bf2(float x, float y) {
    __nv_bfloat162 t = __floats2bfloat162_rn(x, y);
    return *reinterpret_cast<unsigned*>(&t);
}
__device__ __forceinline__ void cp16(uint32_t dst, const void* src) {
    asm volatile("cp.async.cg.shared.global [%0], [%1], 16;"
                 :: "r"(dst), "l"(src) : "memory");
}
#define CP_COMMIT() asm volatile("cp.async.commit_group;" ::: "memory")
#define CP_WAIT0()  asm volatile("cp.async.wait_group 0;" ::: "memory")

__device__ __forceinline__ float dot16(const float* qd, uint4 lo, uint4 hi) {
    uint32_t wbuf[8] = {lo.x, lo.y, lo.z, lo.w, hi.x, hi.y, hi.z, hi.w};
    float d = 0.f;
#pragma unroll
    for (int j = 0; j < 8; j++) {
        float2 f = __half22float2(*reinterpret_cast<const __half2*>(&wbuf[j]));
        d = fmaf(qd[2 * j], f.x, d);
        d = fmaf(qd[2 * j + 1], f.y, d);
    }
    return d;
}
__device__ __forceinline__ void acc16(float* acc, float p, uint4 lo, uint4 hi) {
    uint32_t wbuf[8] = {lo.x, lo.y, lo.z, lo.w, hi.x, hi.y, hi.z, hi.w};
#pragma unroll
    for (int j = 0; j < 8; j++) {
        float2 f = __half22float2(*reinterpret_cast<const __half2*>(&wbuf[j]));
        acc[2 * j]     = fmaf(p, f.x, acc[2 * j]);
        acc[2 * j + 1] = fmaf(p, f.y, acc[2 * j + 1]);
    }
}

// ================= prep: transpose/convert weights =========================
__global__ void k_prep(const float* __restrict__ W0, const float* __restrict__ W1,
                       const float* __restrict__ W2, const float* __restrict__ W3) {
    int j = blockIdx.x * 256 + threadIdx.x;  // [0, 65536)
    int w = j >> 14, rem = j & 16383;
    int n = rem >> 7, kk = rem & 127;
    const float* Wp = (w == 0) ? W0 : (w == 1) ? W1 : (w == 2) ? W2 : W3;
    float val = Wp[kk * 128 + n];
    float hi = __bfloat162float(__float2bfloat16_rn(val));
    g_wt_hi[j] = __float2bfloat16_rn(val);
    g_wt_lo[j] = __float2bfloat16_rn(val - hi);
}

// ================= CSR build ===============================================
// g_cnt is zero on entry: bss-zero on first call, re-zeroed by k_row since.
__global__ void k_hist(const int* __restrict__ rows) {
    int e = blockIdx.x * blockDim.x + threadIdx.x;
    if (e < EE) atomicAdd(&g_cnt[rows[e]], 1);
}

// block-local exclusive scan + zero cnt; last block scans block sums -> boff
__global__ void __launch_bounds__(256) k_scan_block() {
    __shared__ int ws[8];
    __shared__ int islast;
    int b = blockIdx.x, t = threadIdx.x;
    int i0 = b * 1024 + t * 4;
    int v0 = 0, v1 = 0, v2 = 0, v3 = 0;
    if (i0 < NN) {
        if (i0 + 3 < NN) {
            int4 vv = *reinterpret_cast<const int4*>(&g_cnt[i0]);
            v0 = vv.x; v1 = vv.y; v2 = vv.z; v3 = vv.w;
            *reinterpret_cast<int4*>(&g_cnt[i0]) = make_int4(0, 0, 0, 0);
        } else {
            v0 = g_cnt[i0]; g_cnt[i0] = 0;
            if (i0 + 1 < NN) { v1 = g_cnt[i0 + 1]; g_cnt[i0 + 1] = 0; }
            if (i0 + 2 < NN) { v2 = g_cnt[i0 + 2]; g_cnt[i0 + 2] = 0; }
        }
    }
    int tsum = v0 + v1 + v2 + v3;
    int lane = t & 31, wid = t >> 5;
    int x = tsum;
#pragma unroll
    for (int m = 1; m < 32; m <<= 1) {
        int y = __shfl_up_sync(0xffffffffu, x, m);
        if (lane >= m) x += y;
    }
    if (lane == 31) ws[wid] = x;
    __syncthreads();
    if (t == 0) {
        int r = 0;
#pragma unroll
        for (int i = 0; i < 8; i++) { int tmp = ws[i]; ws[i] = r; r += tmp; }
        g_bsum[b] = r;
    }
    __syncthreads();
    int off = ws[wid] + (x - tsum);
    if (i0 < NN) {
        g_rowptr[i0] = off;
        if (i0 + 1 < NN) g_rowptr[i0 + 1] = off + v0;
        if (i0 + 2 < NN) g_rowptr[i0 + 2] = off + v0 + v1;
        if (i0 + 3 < NN) g_rowptr[i0 + 3] = off + v0 + v1 + v2;
    }

    // ---- last arriving block scans the NBLK block sums ----
    if (t == 0) {
        __threadfence();
        int old = atomicAdd(&g_tick, 1);
        islast = (old == NBLK - 1) ? 1 : 0;
        if (islast) g_tick = 0;          // reset for next replay
    }
    __syncthreads();
    if (islast && t < 32) {
        __threadfence();
        int carry = 0;
        for (int bb = 0; bb < NBLK; bb += 32) {
            int i = bb + t;
            int v = (i < NBLK) ? g_bsum[i] : 0;
            int xx = v;
#pragma unroll
            for (int m = 1; m < 32; m <<= 1) {
                int y = __shfl_up_sync(0xffffffffu, xx, m);
                if (t >= m) xx += y;
            }
            if (i < NBLK) g_boff[i] = carry + xx - v;
            carry += __shfl_sync(0xffffffffu, xx, 31);
        }
    }
}

__global__ void k_scatter(const int* __restrict__ rows, const int* __restrict__ cols) {
    int e = blockIdx.x * blockDim.x + threadIdx.x;
    if (e >= EE) return;
    int r = rows[e];
    int pos = g_rowptr[r] + g_boff[r >> 10] + atomicAdd(&g_cnt[r], 1);
    g_csrcol[pos] = cols[e];
}

// ================= fused split-bf16 HMMA GEMM: X->h->{q,k,v} ===============
// 64-row tile, 2 CTA/SM. h epilogue converts acc -> bf16 hi/lo INTO the A
// smem tile (no global h), then Wq/Wk/Wv cycle through the B buffers.
#define ROWB 272
#define SM_AHI  0
#define SM_ALO  (SM_AHI + 64 * ROWB)
#define SM_BHI  (SM_ALO + 64 * ROWB)
#define SM_BLO  (SM_BHI + 128 * ROWB)
#define SM_TOT  (SM_BLO + 128 * ROWB)   // 104448

__device__ __forceinline__ void stage_B_async(uint32_t smb, int t, int widx) {
    const char* bh = reinterpret_cast<const char*>(&g_wt_hi[(size_t)widx * 16384]);
    const char* bl = reinterpret_cast<const char*>(&g_wt_lo[(size_t)widx * 16384]);
#pragma unroll
    for (int i = t; i < 2048; i += 256) {
        uint32_t o = (i >> 4) * ROWB + (i & 15) * 16;
        cp16(smb + SM_BHI + o, bh + i * 16);
        cp16(smb + SM_BLO + o, bl + i * 16);
    }
}

__global__ void __launch_bounds__(256, 2)
k_gemm_fused(const float* __restrict__ X, int M,
             const float* __restrict__ b_in, const float* __restrict__ bq,
             const float* __restrict__ bk, const float* __restrict__ bv,
             float* __restrict__ qo, __half* __restrict__ ko,
             __half* __restrict__ vo) {
    extern __shared__ char sm[];
    const uint32_t smb = smem_u32(sm);
    const int t = threadIdx.x;
    const int wid = t >> 5, lane = t & 31;
    const int mb = wid >> 2, nb = wid & 3;
    const int row0 = blockIdx.x * 64;

    stage_B_async(smb, t, 0);   // W_in
    CP_COMMIT();

    // ---- stage A = X (fp32 -> bf16 hi/lo) ----
#pragma unroll
    for (int i = t; i < 2048; i += 256) {
        int r = i >> 5, c4 = i & 31;
        float4 v = make_float4(0.f, 0.f, 0.f, 0.f);
        if (row0 + r < M)
            v = *reinterpret_cast<const float4*>(&X[(size_t)(row0 + r) * 128 + c4 * 4]);
        float h0 = __bfloat162float(__float2bfloat16_rn(v.x));
        float h1 = __bfloat162float(__float2bfloat16_rn(v.y));
        float h2 = __bfloat162float(__float2bfloat16_rn(v.z));
        float h3 = __bfloat162float(__float2bfloat16_rn(v.w));
        uint32_t o = r * ROWB + c4 * 8;
        *reinterpret_cast<uint2*>(sm + SM_AHI + o) =
            make_uint2(pack_bf2(v.x, v.y), pack_bf2(v.z, v.w));
        *reinterpret_cast<uint2*>(sm + SM_ALO + o) =
            make_uint2(pack_bf2(v.x - h0, v.y - h1), pack_bf2(v.z - h2, v.w - h3));
    }
    CP_WAIT0();
    __syncthreads();

#pragma unroll 1
    for (int wi = 0; wi < 4; wi++) {
        const float* bias = (wi == 0) ? b_in : (wi == 1) ? bq : (wi == 2) ? bk : bv;

        float acc[2][4][4];
#pragma unroll
        for (int i = 0; i < 2; i++)
#pragma unroll
            for (int j = 0; j < 4; j++)
#pragma unroll
                for (int q = 0; q < 4; q++) acc[i][j][q] = 0.f;

#pragma unroll
        for (int ks = 0; ks < 8; ks++) {
            const int k0 = ks * 16;
            uint32_t ah[2][4], al[2][4];
#pragma unroll
            for (int ms = 0; ms < 2; ms++) {
                int r = mb * 32 + ms * 16 + (lane & 7) + ((lane >> 3) & 1) * 8;
                uint32_t off = r * ROWB + (k0 + (lane >> 4) * 8) * 2;
                ldm_x4(ah[ms][0], ah[ms][1], ah[ms][2], ah[ms][3], smb + SM_AHI + off);
                ldm_x4(al[ms][0], al[ms][1], al[ms][2], al[ms][3], smb + SM_ALO + off);
            }
            uint32_t bh[4][2], bl[4][2];
#pragma unroll
            for (int ng = 0; ng < 2; ng++) {
                int r = nb * 32 + ng * 16 + (lane & 7) + ((lane >= 16) ? 8 : 0);
                uint32_t off = r * ROWB + (k0 + ((lane >> 3) & 1) * 8) * 2;
                uint32_t r0, r1, r2, r3;
                ldm_x4(r0, r1, r2, r3, smb + SM_BHI + off);
                bh[2 * ng][0] = r0; bh[2 * ng][1] = r1;
                bh[2 * ng + 1][0] = r2; bh[2 * ng + 1][1] = r3;
                ldm_x4(r0, r1, r2, r3, smb + SM_BLO + off);
                bl[2 * ng][0] = r0; bl[2 * ng][1] = r1;
                bl[2 * ng + 1][0] = r2; bl[2 * ng + 1][1] = r3;
            }
#pragma unroll
            for (int ms = 0; ms < 2; ms++)
#pragma unroll
                for (int nt = 0; nt < 4; nt++) {
                    mma_bf16(acc[ms][nt], ah[ms], bh[nt][0], bh[nt][1]);
                    mma_bf16(acc[ms][nt], ah[ms], bl[nt][0], bl[nt][1]);
                    mma_bf16(acc[ms][nt], al[ms], bh[nt][0], bh[nt][1]);
                }
        }

        __syncthreads();   // all warps done reading A and B smem
        if (wi < 3) {
            stage_B_async(smb, t, wi + 1);
            CP_COMMIT();
        }

        // ---- epilogue ----
        const int g = lane >> 2, tq = lane & 3;
#pragma unroll
        for (int nt = 0; nt < 4; nt++) {
            int col = nb * 32 + nt * 8 + tq * 2;
            float b0 = __ldg(&bias[col]), b1 = __ldg(&bias[col + 1]);
#pragma unroll
            for (int ms = 0; ms < 2; ms++) {
#pragma unroll
                for (int hh = 0; hh < 2; hh++) {
                    int rl = mb * 32 + ms * 16 + g + hh * 8;  // local row
                    float o0 = acc[ms][nt][2 * hh + 0] + b0;
                    float o1 = acc[ms][nt][2 * hh + 1] + b1;
                    if (wi == 0) {
                        // h -> bf16 hi/lo back into the A smem tile
                        float f0 = __bfloat162float(__float2bfloat16_rn(o0));
                        float f1 = __bfloat162float(__float2bfloat16_rn(o1));
                        uint32_t o = rl * ROWB + col * 2;
                        *reinterpret_cast<uint32_t*>(sm + SM_AHI + o) = pack_bf2(o0, o1);
                        *reinterpret_cast<uint32_t*>(sm + SM_ALO + o) =
                            pack_bf2(o0 - f0, o1 - f1);
                    } else {
                        int r = row0 + rl;
                        if (r < M) {
                            if (wi == 1) {
                                *reinterpret_cast<float2*>(&qo[(size_t)r * 128 + col]) =
                                    make_float2(0.25f * o0, 0.25f * o1);
                            } else {
                                __half* C = (wi == 2) ? ko : vo;
                                *reinterpret_cast<__half2*>(&C[(size_t)r * 128 + col]) =
                                    __floats2half2_rn(o0, o1);
                            }
                        }
                    }
                }
            }
        }
        if (wi < 3) {
            CP_WAIT0();
            __syncthreads();   // As rewrite (wi=0) + next B visible to all
        }
    }
}

// ================= permute k/v to head-major via smem ======================
// canonical col c -> head-major p = (c%8)*16 + c/8
#define PBLK 3125   // NN/32
__global__ void __launch_bounds__(256) k_perm() {
    __shared__ __align__(16) __half smh[32][136];
    const int t = threadIdx.x;
    const int tensor = blockIdx.x / PBLK;
    const int row0 = (blockIdx.x - tensor * PBLK) * 32;
    const int r = t >> 3, h = t & 7;

    const __half* srcg = (tensor == 0) ? g_k : g_v;
    __half* dstg = (tensor == 0) ? g_k2 : g_v2;
    const uint4* src = reinterpret_cast<const uint4*>(&srcg[(size_t)row0 * 128]);
#pragma unroll
    for (int j = 0; j < 2; j++) {
        int i = t + 256 * j;               // 512 uint4 = 32 rows x 16
        uint4 v = src[i];
        *reinterpret_cast<uint4*>(&smh[i >> 4][(i & 15) * 8]) = v;
    }
    __syncthreads();
    __align__(16) __half buf[16];
#pragma unroll
    for (int m = 0; m < 16; m++) buf[m] = smh[r][m * 8 + h];
    uint4* dst = reinterpret_cast<uint4*>(&dstg[(size_t)(row0 + r) * 128 + h * 16]);
    dst[0] = reinterpret_cast<uint4*>(buf)[0];
    dst[1] = reinterpret_cast<uint4*>(buf)[1];
}

// ================= fused per-row attention: head-major, lane=(group,head) ==
__global__ void __launch_bounds__(256)
k_row(float* __restrict__ out) {
    int w = (blockIdx.x * blockDim.x + threadIdx.x) >> 5;
    if (w >= NN) return;
    const int lane = threadIdx.x & 31;
    const int g = lane >> 3, h = lane & 7;
    const int s = g_rowptr[w] + g_boff[w >> 10];
    const int e = (w + 1 < NN) ? (g_rowptr[w + 1] + g_boff[(w + 1) >> 10]) : EE;

    if (lane == 0) g_cnt[w] = 0;   // reset for next run's k_hist

    float qd[16];   // strided head-major view of canonical q (lanes broadcast)
#pragma unroll
    for (int j = 0; j < 16; j++)
        qd[j] = __ldg(&g_q[(size_t)w * 128 + j * 8 + h]);

    float t = 0.f;
    float acc[16];
#pragma unroll
    for (int j = 0; j < 16; j++) acc[j] = 0.f;

    for (int i = s + g; i < e; i += 8) {   // 2 edges in flight per lane
        int ib = i + 4;
        bool has_b = ib < e;
        int ca = __ldg(&g_csrcol[i]);
        int cb = __ldg(&g_csrcol[has_b ? ib : i]);
        const uint4* kap = reinterpret_cast<const uint4*>(&g_k2[(size_t)ca * 128 + h * 16]);
        const uint4* kbp = reinterpret_cast<const uint4*>(&g_k2[(size_t)cb * 128 + h * 16]);
        const uint4* vap = reinterpret_cast<const uint4*>(&g_v2[(size_t)ca * 128 + h * 16]);
        const uint4* vbp = reinterpret_cast<const uint4*>(&g_v2[(size_t)cb * 128 + h * 16]);
        uint4 ka0 = kap[0], ka1 = kap[1];
        uint4 kb0 = kbp[0], kb1 = kbp[1];
        uint4 va0 = vap[0], va1 = vap[1];
        uint4 vb0 = vbp[0], vb1 = vbp[1];

        float da = dot16(qd, ka0, ka1);
        float db = dot16(qd, kb0, kb1);
        float pa = __expf(da);
        float pb = has_b ? __expf(db) : 0.f;
        t += pa + pb;
        acc16(acc, pa, va0, va1);
        acc16(acc, pb, vb0, vb1);
    }

    t += __shfl_xor_sync(0xffffffffu, t, 8);
    t += __shfl_xor_sync(0xffffffffu, t, 16);
#pragma unroll
    for (int j = 0; j < 16; j++) {
        acc[j] += __shfl_xor_sync(0xffffffffu, acc[j], 8);
        acc[j] += __shfl_xor_sync(0xffffffffu, acc[j], 16);
    }
    float inv = (t > 0.f) ? 1.0f / t : 0.f;

    // out layout [n][d][h]: lane (g,h) writes d = g*4 .. g*4+3
#pragma unroll
    for (int j = 0; j < 4; j++) {
        int d = g * 4 + j;
        out[(size_t)w * 128 + d * 8 + h] = acc[d] * inv;
    }
}

// ================= launch ===================================================
extern "C" void kernel_launch(void* const* d_in, const int* in_sizes, int n_in,
                              void* d_out, int out_size) {
    const float* X    = (const float*)d_in[0];
    const int*   rows = (const int*)d_in[1];
    const int*   cols = (const int*)d_in[2];
    const float* W_in = (const float*)d_in[3];
    const float* b_in = (const float*)d_in[4];
    const float* Wq   = (const float*)d_in[5];
    const float* bq   = (const float*)d_in[6];
    const float* Wk   = (const float*)d_in[7];
    const float* bk   = (const float*)d_in[8];
    const float* Wv   = (const float*)d_in[9];
    const float* bv   = (const float*)d_in[10];
    float* out = (float*)d_out;
    (void)in_sizes; (void)n_in; (void)out_size;

    // one-time stream/event setup (no device memory allocation involved)
    static cudaStream_t s1 = nullptr;
    static cudaEvent_t ev_fork = nullptr, ev_join = nullptr;
    if (s1 == nullptr) {
        cudaStreamCreateWithFlags(&s1, cudaStreamNonBlocking);
        cudaEventCreateWithFlags(&ev_fork, cudaEventDisableTiming);
        cudaEventCreateWithFlags(&ev_join, cudaEventDisableTiming);
    }

    cudaFuncSetAttribute(k_gemm_fused, cudaFuncAttributeMaxDynamicSharedMemorySize,
                         SM_TOT);

    void *pq, *pkk, *pv;
    cudaGetSymbolAddress(&pq, g_q);
    cudaGetSymbolAddress(&pkk, g_k);
    cudaGetSymbolAddress(&pv, g_v);

    const int gb = (NN + 63) / 64;

    // ---- fork: CSR chain on s1, dense chain on main stream ----
    cudaEventRecord(ev_fork, 0);
    cudaStreamWaitEvent(s1, ev_fork, 0);

    k_hist<<<(EE + 255) / 256, 256, 0, s1>>>(rows);                // 0 (s1)
    k_scan_block<<<NBLK, 256, 0, s1>>>();                          // 1 (s1)
    k_prep<<<256, 256>>>(W_in, Wq, Wk, Wv);                        // 2 (main)
    k_gemm_fused<<<gb, 256, SM_TOT>>>(X, NN, b_in, bq, bk, bv,     // 3 (ncu)
                                      (float*)pq, (__half*)pkk, (__half*)pv);
    k_scatter<<<(EE + 255) / 256, 256, 0, s1>>>(rows, cols);       // 4 (s1)
    cudaEventRecord(ev_join, s1);

    k_perm<<<2 * PBLK, 256>>>();                                   // 5 (main)

    // ---- join: k_row needs CSR + perm ----
    cudaStreamWaitEvent(0, ev_join, 0);
    k_row<<<(NN * 32 + 255) / 256, 256>>>(out);                    // 6 (main)
}